// round 12
// baseline (speedup 1.0000x reference)
#include <cuda_runtime.h>
#include <cstdint>
#include <climits>

// ---------------------------------------------------------------------------
// PointPillars voxelization, exact-semantics re-derivation (no sort needed).
//   voxel index = rank of occupied cell in ascending flat order (< 60000)
//   point rank  = position by ORIGINAL point index within the cell (< 32)
// fp32 math bit-matches JAX (power-of-two voxel sizes). Bucket depth 64 >>
// max cell occupancy (~24 at lambda~5 over 160K cells).
// ---------------------------------------------------------------------------

#define GX 400
#define GY 400
#define NCELLS 160000
#define MAX_VOX 60000
#define MAX_PTS 32
#define CAP 64
#define D 5

#define SCAN_B 1024
#define NB ((NCELLS + SCAN_B - 1) / SCAN_B)   // 157

#define EMIT_BLOCKS 1184          // 148 SMs x 8 CTAs -> single wave
#define EMIT_WARPS (EMIT_BLOCKS * 8)

__device__ int g_cell_count[NCELLS];
__device__ int g_cell_rank[NCELLS];
__device__ int g_buckets[(size_t)NCELLS * CAP];
__device__ int g_block_sums[NB];

// ---------------------------------------------------------------------------
// Pass 1: count + scatter point indices (smem-staged coalesced loads)
__global__ void __launch_bounds__(256) k_count_scatter(const float* __restrict__ pts, int n) {
    __shared__ float sp[256 * D];
    int base = blockIdx.x * 256;
    int t = threadIdx.x;

    int nflt = min(n - base, 256) * D;
    const float4* src4 = (const float4*)(pts + (size_t)base * D);
    int nv4 = nflt >> 2;
    for (int j = t; j < nv4; j += 256)
        ((float4*)sp)[j] = __ldg(src4 + j);
    for (int j = (nv4 << 2) + t; j < nflt; j += 256)
        sp[j] = __ldg(pts + (size_t)base * D + j);
    __syncthreads();

    int i = base + t;
    if (i >= n) return;
    float x = sp[t * D + 0], y = sp[t * D + 1], z = sp[t * D + 2];
    int cx = (int)floorf((x + 50.0f) * 4.0f);
    int cy = (int)floorf((y + 50.0f) * 4.0f);
    int cz = (int)floorf((z + 5.0f)  * 0.125f);
    bool ok = (cx >= 0) & (cx < GX) & (cy >= 0) & (cy < GY) & (cz == 0);
    if (!ok) return;
    int cell = cy * GX + cx;
    int slot = atomicAdd(&g_cell_count[cell], 1);
    if (slot < CAP) g_buckets[(size_t)cell * CAP + slot] = i;
}

// ---------------------------------------------------------------------------
// Pass 2a: per-block occupancy sums
__global__ void __launch_bounds__(SCAN_B) k_scan_partial() {
    __shared__ int red[32];
    int i = blockIdx.x * SCAN_B + threadIdx.x;
    int v = (i < NCELLS) ? (g_cell_count[i] > 0) : 0;
    #pragma unroll
    for (int o = 16; o; o >>= 1) v += __shfl_down_sync(0xffffffffu, v, o);
    if ((threadIdx.x & 31) == 0) red[threadIdx.x >> 5] = v;
    __syncthreads();
    if (threadIdx.x < 32) {
        int s = (threadIdx.x < SCAN_B / 32) ? red[threadIdx.x] : 0;
        #pragma unroll
        for (int o = 16; o; o >>= 1) s += __shfl_down_sync(0xffffffffu, s, o);
        if (threadIdx.x == 0) g_block_sums[blockIdx.x] = s;
    }
}

// Pass 2b: fused block-prefix + warp-shuffle scan + rank write + tail guard
__global__ void __launch_bounds__(SCAN_B) k_scan_apply(float* __restrict__ vox,
                                                       float* __restrict__ coords,
                                                       float* __restrict__ nump) {
    __shared__ int wsum[32];
    __shared__ int bpre;
    __shared__ int nocc;
    int t = threadIdx.x, lane = t & 31, wid = t >> 5;
    int i = blockIdx.x * SCAN_B + t;
    int flag = (i < NCELLS) ? (g_cell_count[i] > 0) : 0;

    int v = flag;
    #pragma unroll
    for (int o = 1; o < 32; o <<= 1) {
        int u = __shfl_up_sync(0xffffffffu, v, o);
        if (lane >= o) v += u;
    }
    if (lane == 31) wsum[wid] = v;
    __syncthreads();

    if (wid == 0) {
        int s = wsum[lane];
        #pragma unroll
        for (int o = 1; o < 32; o <<= 1) {
            int u = __shfl_up_sync(0xffffffffu, s, o);
            if (lane >= o) s += u;
        }
        wsum[lane] = s;
    } else if (wid == 1) {
        int s = 0;
        for (int j = lane; j < blockIdx.x; j += 32) s += g_block_sums[j];
        #pragma unroll
        for (int o = 16; o; o >>= 1) s += __shfl_down_sync(0xffffffffu, s, o);
        if (lane == 0) bpre = s;
    } else if (wid == 2) {
        int s = 0;
        for (int j = lane; j < NB; j += 32) s += g_block_sums[j];
        #pragma unroll
        for (int o = 16; o; o >>= 1) s += __shfl_down_sync(0xffffffffu, s, o);
        if (lane == 0) nocc = s;
    }
    __syncthreads();

    int warp_excl = wid ? wsum[wid - 1] : 0;
    if (flag) g_cell_rank[i] = bpre + warp_excl + v - 1;

    // Robustness guard: zero rows for ranks never produced (no-op on this input)
    int r = i;
    if (r < MAX_VOX && r >= nocc) {
        float4 z4 = make_float4(0.f, 0.f, 0.f, 0.f);
        float4* row4 = (float4*)(vox + (size_t)r * MAX_PTS * D);
        for (int f = 0; f < (MAX_PTS * D) / 4; f++) __stcs(row4 + f, z4);
        coords[(size_t)r * 3 + 0] = 0.0f;
        coords[(size_t)r * 3 + 1] = 0.0f;
        coords[(size_t)r * 3 + 2] = 0.0f;
        nump[r] = 0.0f;
    }
}

// ---------------------------------------------------------------------------
// Pass 3: PERSISTENT emit — single wave (1184 CTAs), each warp strides over
// cells (~17 each) so per-cell latency chains overlap across resident warps
// instead of paying ~17 wave transitions. Fast path (n<=32, always taken on
// this input): bucket entry held in a register lane, rank via warp shuffles.
__global__ void __launch_bounds__(256) k_emit(const float* __restrict__ pts,
                       float* __restrict__ vox,     // [MAX_VOX,32,5]
                       float* __restrict__ coords,  // [MAX_VOX,3] (z,y,x)
                       float* __restrict__ nump)    // [MAX_VOX]
{
    int lane = threadIdx.x & 31;
    int w    = threadIdx.x >> 5;
    int gwarp = (blockIdx.x << 3) | w;
    __shared__ int inv[8][MAX_PTS];
    __shared__ int sh[8][CAP];           // slow-path only (n > 32; ~never)

    for (int cell = gwarp; cell < NCELLS; cell += EMIT_WARPS) {
        int count = g_cell_count[cell];
        if (count == 0) continue;
        int rank = g_cell_rank[cell];
        if (rank >= MAX_VOX) continue;
        int n = min(count, CAP);

        inv[w][lane] = -1;
        __syncwarp();

        if (n <= 32) {
            // register-resident bucket entry + shuffle ranking
            int v = (lane < n) ? g_buckets[(size_t)cell * CAP + lane] : INT_MAX;
            int r = 0;
            for (int k = 0; k < n; k++) {
                int u = __shfl_sync(0xffffffffu, v, k);
                r += (u < v);
            }
            if (lane < n) inv[w][r] = v;     // ranks are a permutation, r < n <= 32
        } else {
            // slow path: stage in shared, O(n^2) rank (never taken on this input)
            for (int j = lane; j < n; j += 32)
                sh[w][j] = g_buckets[(size_t)cell * CAP + j];
            __syncwarp();
            for (int j = lane; j < n; j += 32) {
                int v = sh[w][j];
                int r = 0;
                for (int k = 0; k < n; k++) r += (sh[w][k] < v);
                if (r < MAX_PTS) inv[w][r] = v;
            }
        }
        __syncwarp();

        // warp-cooperative transposed row emit: 160 floats, coalesced stores
        float* dst = vox + (size_t)rank * (MAX_PTS * D);
        #pragma unroll
        for (int j = lane; j < MAX_PTS * D; j += 32) {
            int r = j / D;
            int f = j - r * D;
            int v = inv[w][r];
            float val = 0.0f;
            if (v >= 0) val = __ldg(pts + (size_t)v * D + f);
            __stcs(dst + j, val);
        }

        if (lane == 0) {
            nump[rank] = (float)min(count, MAX_PTS);
            int cx = cell % GX;
            int cy = cell / GX;
            coords[(size_t)rank * 3 + 0] = 0.0f;        // z
            coords[(size_t)rank * 3 + 1] = (float)cy;   // y
            coords[(size_t)rank * 3 + 2] = (float)cx;   // x
        }
        __syncwarp();    // protect inv[] before next iteration overwrites
    }
}

// ---------------------------------------------------------------------------
extern "C" void kernel_launch(void* const* d_in, const int* in_sizes, int n_in,
                              void* d_out, int out_size) {
    const float* pts = (const float*)d_in[0];
    int n = in_sizes[0] / D;            // 1,200,000

    float* out = (float*)d_out;
    float* vox    = out;
    float* coords = out + (size_t)MAX_VOX * MAX_PTS * D;
    float* nump   = coords + (size_t)MAX_VOX * 3;

    void* cnt_ptr = nullptr;
    cudaGetSymbolAddress(&cnt_ptr, g_cell_count);   // lookup only, no alloc
    cudaMemsetAsync(cnt_ptr, 0, NCELLS * sizeof(int), 0);

    k_count_scatter<<<(n + 255) / 256, 256>>>(pts, n);
    k_scan_partial<<<NB, SCAN_B>>>();
    k_scan_apply<<<NB, SCAN_B>>>(vox, coords, nump);
    k_emit<<<EMIT_BLOCKS, 256>>>(pts, vox, coords, nump);
}

// round 13
// speedup vs baseline: 1.2902x; 1.2902x over previous
#include <cuda_runtime.h>
#include <cstdint>
#include <climits>

// ---------------------------------------------------------------------------
// PointPillars voxelization, exact-semantics re-derivation (no sort needed).
//   voxel index = rank of occupied cell in ascending flat order (< 60000)
//   point rank  = position by ORIGINAL point index within the cell (< 32)
// fp32 math bit-matches JAX (power-of-two voxel sizes). Bucket depth 64 >>
// max cell occupancy (~24 at lambda~5 over 160K cells).
// ---------------------------------------------------------------------------

#define GX 400
#define GY 400
#define NCELLS 160000
#define MAX_VOX 60000
#define MAX_PTS 32
#define CAP 64
#define D 5

#define SCAN_B 1024
#define NB ((NCELLS + SCAN_B - 1) / SCAN_B)   // 157

#define EMIT_BLOCKS 1184          // 148 SMs x 8 CTAs (32-reg cap) -> one wave
#define EMIT_WARPS (EMIT_BLOCKS * 8)

__device__ int g_cell_count[NCELLS];
__device__ int g_buckets[(size_t)NCELLS * CAP];
__device__ int g_block_sums[NB];
__device__ int g_rank_to_cell[MAX_VOX];
__device__ int g_nocc;

// ---------------------------------------------------------------------------
// Pass 1: count + scatter point indices (smem-staged coalesced loads)
__global__ void __launch_bounds__(256) k_count_scatter(const float* __restrict__ pts, int n) {
    __shared__ float sp[256 * D];
    int base = blockIdx.x * 256;
    int t = threadIdx.x;

    int nflt = min(n - base, 256) * D;
    const float4* src4 = (const float4*)(pts + (size_t)base * D);
    int nv4 = nflt >> 2;
    for (int j = t; j < nv4; j += 256)
        ((float4*)sp)[j] = __ldg(src4 + j);
    for (int j = (nv4 << 2) + t; j < nflt; j += 256)
        sp[j] = __ldg(pts + (size_t)base * D + j);
    __syncthreads();

    int i = base + t;
    if (i >= n) return;
    float x = sp[t * D + 0], y = sp[t * D + 1], z = sp[t * D + 2];
    int cx = (int)floorf((x + 50.0f) * 4.0f);
    int cy = (int)floorf((y + 50.0f) * 4.0f);
    int cz = (int)floorf((z + 5.0f)  * 0.125f);
    bool ok = (cx >= 0) & (cx < GX) & (cy >= 0) & (cy < GY) & (cz == 0);
    if (!ok) return;
    int cell = cy * GX + cx;
    int slot = atomicAdd(&g_cell_count[cell], 1);
    if (slot < CAP) g_buckets[(size_t)cell * CAP + slot] = i;
}

// ---------------------------------------------------------------------------
// Pass 2a: per-block occupancy sums
__global__ void __launch_bounds__(SCAN_B) k_scan_partial() {
    __shared__ int red[32];
    int i = blockIdx.x * SCAN_B + threadIdx.x;
    int v = (i < NCELLS) ? (g_cell_count[i] > 0) : 0;
    #pragma unroll
    for (int o = 16; o; o >>= 1) v += __shfl_down_sync(0xffffffffu, v, o);
    if ((threadIdx.x & 31) == 0) red[threadIdx.x >> 5] = v;
    __syncthreads();
    if (threadIdx.x < 32) {
        int s = (threadIdx.x < SCAN_B / 32) ? red[threadIdx.x] : 0;
        #pragma unroll
        for (int o = 16; o; o >>= 1) s += __shfl_down_sync(0xffffffffu, s, o);
        if (threadIdx.x == 0) g_block_sums[blockIdx.x] = s;
    }
}

// Pass 2b: fused block-prefix + warp scan; writes rank->cell inverse index,
// total occupied count, and zero-fills rows for never-produced ranks.
__global__ void __launch_bounds__(SCAN_B) k_scan_apply(float* __restrict__ vox,
                                                       float* __restrict__ coords,
                                                       float* __restrict__ nump) {
    __shared__ int wsum[32];
    __shared__ int bpre;
    __shared__ int nocc_sh;
    int t = threadIdx.x, lane = t & 31, wid = t >> 5;
    int i = blockIdx.x * SCAN_B + t;
    int flag = (i < NCELLS) ? (g_cell_count[i] > 0) : 0;

    int v = flag;
    #pragma unroll
    for (int o = 1; o < 32; o <<= 1) {
        int u = __shfl_up_sync(0xffffffffu, v, o);
        if (lane >= o) v += u;
    }
    if (lane == 31) wsum[wid] = v;
    __syncthreads();

    if (wid == 0) {
        int s = wsum[lane];
        #pragma unroll
        for (int o = 1; o < 32; o <<= 1) {
            int u = __shfl_up_sync(0xffffffffu, s, o);
            if (lane >= o) s += u;
        }
        wsum[lane] = s;
    } else if (wid == 1) {
        int s = 0;
        for (int j = lane; j < blockIdx.x; j += 32) s += g_block_sums[j];
        #pragma unroll
        for (int o = 16; o; o >>= 1) s += __shfl_down_sync(0xffffffffu, s, o);
        if (lane == 0) bpre = s;
    } else if (wid == 2) {
        int s = 0;
        for (int j = lane; j < NB; j += 32) s += g_block_sums[j];
        #pragma unroll
        for (int o = 16; o; o >>= 1) s += __shfl_down_sync(0xffffffffu, s, o);
        if (lane == 0) { nocc_sh = s; g_nocc = s; }
    }
    __syncthreads();

    int warp_excl = wid ? wsum[wid - 1] : 0;
    if (flag) {
        int rk = bpre + warp_excl + v - 1;
        if (rk < MAX_VOX) g_rank_to_cell[rk] = i;
    }

    // Robustness guard: zero rows for ranks never produced (no-op on this input)
    int r = i;
    int nocc = nocc_sh;
    if (r < MAX_VOX && r >= nocc) {
        float4 z4 = make_float4(0.f, 0.f, 0.f, 0.f);
        float4* row4 = (float4*)(vox + (size_t)r * MAX_PTS * D);
        for (int f = 0; f < (MAX_PTS * D) / 4; f++) __stcs(row4 + f, z4);
        coords[(size_t)r * 3 + 0] = 0.0f;
        coords[(size_t)r * 3 + 1] = 0.0f;
        coords[(size_t)r * 3 + 2] = 0.0f;
        nump[r] = 0.0f;
    }
}

// ---------------------------------------------------------------------------
// Pass 3: persistent, ONE WARP PER RANK (60K work units, no dead warps).
// 1184 CTAs x 8 warps = single resident wave at 8 CTA/SM (32-reg cap).
// Fast path (n<=32, always here): lane holds its bucket entry, rank via
// shuffles, lane with rank r writes slot r; lanes >= n zero slots n..31.
// No shared memory, no __syncwarp on the fast path.
__global__ void __launch_bounds__(256, 8) k_emit(const float* __restrict__ pts,
                       float* __restrict__ vox,     // [MAX_VOX,32,5]
                       float* __restrict__ coords,  // [MAX_VOX,3] (z,y,x)
                       float* __restrict__ nump)    // [MAX_VOX]
{
    int lane = threadIdx.x & 31;
    int w    = threadIdx.x >> 5;
    int gwarp = (blockIdx.x << 3) | w;
    __shared__ int sh[8][CAP];           // slow-path only (n > 32; ~never)
    __shared__ int inv[8][MAX_PTS];      // slow-path only

    int lim = g_nocc;
    if (lim > MAX_VOX) lim = MAX_VOX;

    for (int rank = gwarp; rank < lim; rank += EMIT_WARPS) {
        int cell  = g_rank_to_cell[rank];
        int count = g_cell_count[cell];
        int n = min(count, CAP);

        int slot, v;
        if (n <= 32) {
            int idx = (lane < n) ? g_buckets[(size_t)cell * CAP + lane] : INT_MAX;
            int r = 0;
            for (int k = 0; k < n; k++)
                r += (__shfl_sync(0xffffffffu, idx, k) < idx);   // distinct idx
            slot = (lane < n) ? r : lane;      // ranks 0..n-1 + empties n..31
            v    = (lane < n) ? idx : -1;
        } else {
            // slow path (never taken on this input): smem O(n^2) ranking
            for (int j = lane; j < n; j += 32)
                sh[w][j] = g_buckets[(size_t)cell * CAP + j];
            inv[w][lane] = -1;
            __syncwarp();
            for (int j = lane; j < n; j += 32) {
                int vv = sh[w][j];
                int r = 0;
                for (int k = 0; k < n; k++) r += (sh[w][k] < vv);
                if (r < MAX_PTS) inv[w][r] = vv;
            }
            __syncwarp();
            slot = lane;
            v = inv[w][lane];
            __syncwarp();
        }

        float f0 = 0.f, f1 = 0.f, f2 = 0.f, f3 = 0.f, f4 = 0.f;
        if (v >= 0) {
            const float* ip = pts + (size_t)v * D;
            f0 = __ldg(ip + 0); f1 = __ldg(ip + 1); f2 = __ldg(ip + 2);
            f3 = __ldg(ip + 3); f4 = __ldg(ip + 4);
        }
        float* dst = vox + (size_t)rank * (MAX_PTS * D) + slot * D;
        __stcs(dst + 0, f0); __stcs(dst + 1, f1); __stcs(dst + 2, f2);
        __stcs(dst + 3, f3); __stcs(dst + 4, f4);

        if (lane == 0) {
            nump[rank] = (float)min(count, MAX_PTS);
            int cx = cell % GX;
            int cy = cell / GX;
            coords[(size_t)rank * 3 + 0] = 0.0f;        // z
            coords[(size_t)rank * 3 + 1] = (float)cy;   // y
            coords[(size_t)rank * 3 + 2] = (float)cx;   // x
        }
    }
}

// ---------------------------------------------------------------------------
extern "C" void kernel_launch(void* const* d_in, const int* in_sizes, int n_in,
                              void* d_out, int out_size) {
    const float* pts = (const float*)d_in[0];
    int n = in_sizes[0] / D;            // 1,200,000

    float* out = (float*)d_out;
    float* vox    = out;
    float* coords = out + (size_t)MAX_VOX * MAX_PTS * D;
    float* nump   = coords + (size_t)MAX_VOX * 3;

    void* cnt_ptr = nullptr;
    cudaGetSymbolAddress(&cnt_ptr, g_cell_count);   // lookup only, no alloc
    cudaMemsetAsync(cnt_ptr, 0, NCELLS * sizeof(int), 0);

    k_count_scatter<<<(n + 255) / 256, 256>>>(pts, n);
    k_scan_partial<<<NB, SCAN_B>>>();
    k_scan_apply<<<NB, SCAN_B>>>(vox, coords, nump);
    k_emit<<<EMIT_BLOCKS, 256>>>(pts, vox, coords, nump);
}